// round 11
// baseline (speedup 1.0000x reference)
#include <cuda_runtime.h>
#include <cuda_fp16.h>
#include <cstdint>

// Problem constants
#define B_ 4
#define N_ 4096
#define D_ 512
#define K_ 32
#define TILES 32            // N_/128
#define PAIRS 528           // TILES*(TILES+1)/2

#define THRESH 0.09f
#define CAND_MAX 256
#define NROWS (B_ * N_)     // 16384

// Scratch (device globals — no runtime allocation allowed)
__device__ __align__(128) __half g_h[(size_t)B_ * N_ * D_];           // 16 MB
__device__ __align__(128) __half g_l[(size_t)B_ * N_ * D_];           // 16 MB
__device__ __align__(128) int   g_cnt[NROWS];                         // 64 KB
__device__ __align__(128) float g_candV[(size_t)NROWS * CAND_MAX];    // 16.8 MB
__device__ __align__(128) int   g_candI[(size_t)NROWS * CAND_MAX];    // 16.8 MB

// ---------------------------------------------------------------------------
// Portable PTX helpers (compute_103-safe)
// ---------------------------------------------------------------------------
__device__ __forceinline__ uint32_t smem_u32(const void* p) {
    uint32_t a;
    asm("{ .reg .u64 t; cvta.to.shared.u64 t, %1; cvt.u32.u64 %0, t; }"
        : "=r"(a) : "l"(p));
    return a;
}

#define SWZ(off) ((off) ^ (((off) >> 3) & 0x70))

#define CP_ASYNC16(dst_u32, src_ptr) \
    asm volatile("cp.async.cg.shared.global [%0], [%1], 16;" \
                 :: "r"(dst_u32), "l"(src_ptr) : "memory")
#define CP_COMMIT() asm volatile("cp.async.commit_group;" ::: "memory")
#define CP_WAIT(n)  asm volatile("cp.async.wait_group %0;" :: "n"(n) : "memory")

#define LDSM_X4(r0, r1, r2, r3, addr) \
    asm volatile("ldmatrix.sync.aligned.m8n8.x4.shared.b16 {%0,%1,%2,%3}, [%4];" \
                 : "=r"(r0), "=r"(r1), "=r"(r2), "=r"(r3) : "r"(addr))

#define MMA16816F16(c, a, b) \
    asm volatile("mma.sync.aligned.m16n8k16.row.col.f32.f16.f16.f32 " \
                 "{%0,%1,%2,%3}, {%4,%5,%6,%7}, {%8,%9}, {%0,%1,%2,%3};" \
                 : "+f"((c)[0]), "+f"((c)[1]), "+f"((c)[2]), "+f"((c)[3]) \
                 : "r"((a)[0]), "r"((a)[1]), "r"((a)[2]), "r"((a)[3]), \
                   "r"((b)[0]), "r"((b)[1]))

// ---------------------------------------------------------------------------
// Kernel 1: row L2-normalization + fp16 2-limb split (unchanged).
// ---------------------------------------------------------------------------
__global__ void __launch_bounds__(128) normalize_kernel(const float* __restrict__ x) {
    int row = blockIdx.x;
    const float* xr = x + (size_t)row * D_;
    int t = threadIdx.x;

    float4 v = ((const float4*)xr)[t];
    float ss = v.x * v.x + v.y * v.y + v.z * v.z + v.w * v.w;
    #pragma unroll
    for (int o = 16; o; o >>= 1) ss += __shfl_xor_sync(0xffffffffu, ss, o);

    __shared__ float wsum[4];
    if ((t & 31) == 0) wsum[t >> 5] = ss;
    __syncthreads();
    float total = wsum[0] + wsum[1] + wsum[2] + wsum[3];
    float scale = 1.0f / fmaxf(sqrtf(total), 1e-12f);

    float xn[4] = {v.x * scale, v.y * scale, v.z * scale, v.w * scale};
    unsigned short hs[4], ls[4];
    #pragma unroll
    for (int q = 0; q < 4; q++) {
        __half h = __float2half_rn(xn[q]);
        float r1 = xn[q] - __half2float(h);
        __half l = __float2half_rn(r1);
        hs[q] = __half_as_ushort(h);
        ls[q] = __half_as_ushort(l);
    }
    uint2 hp, lp;
    hp.x = (uint32_t)hs[0] | ((uint32_t)hs[1] << 16);
    hp.y = (uint32_t)hs[2] | ((uint32_t)hs[3] << 16);
    lp.x = (uint32_t)ls[0] | ((uint32_t)ls[1] << 16);
    lp.y = (uint32_t)ls[2] | ((uint32_t)ls[3] << 16);
    ((uint2*)(g_h + (size_t)row * D_))[t] = hp;
    ((uint2*)(g_l + (size_t)row * D_))[t] = lp;
}

// ---------------------------------------------------------------------------
// Kernel 2: symmetric batched GEMM (fp16 2-limb 3-pass HMMA) with FUSED
// candidate extraction: no g_sim materialization. Each accumulator value
// > THRESH is appended (atomically) to its row's candidate list; mirror
// candidates come from the same registers for off-diagonal tiles.
// Accumulation order identical to R10 -> candidate values bitwise same.
// ---------------------------------------------------------------------------
#define CHUNK_BYTES 16384                 // 128 rows x 64 fp16 (128B/row)
#define SMEM_TOTAL  (4 * CHUNK_BYTES)     // 64 KB (single buffer; 2 CTAs/SM)

__global__ void __launch_bounds__(256, 2) gemm_hmma_kernel() {
    extern __shared__ __align__(1024) char smem[];
    uint32_t sbase = smem_u32(smem);
    int tid = threadIdx.x;
    int wid = tid >> 5;
    int lane = tid & 31;

    int bidx = blockIdx.x;
    int b = bidx / PAIRS;
    int u = bidx % PAIRS;
    int ti = 0;
    while (u >= TILES - ti) { u -= TILES - ti; ti++; }
    int tj = ti + u;                      // tj >= ti

    size_t aoff = ((size_t)b * N_ + (size_t)ti * 128) * D_;
    size_t boff = ((size_t)b * N_ + (size_t)tj * 128) * D_;
    const __half* srcs[4] = {
        g_h + aoff, g_l + aoff,           // A limbs
        g_h + boff, g_l + boff            // B limbs
    };

    int wm = wid & 1;                     // 2 warps in M (64 rows each)
    int wn = wid >> 1;                    // 4 warps in N (32 cols each)

    float acc[4][4][4];
    #pragma unroll
    for (int mt = 0; mt < 4; mt++)
        #pragma unroll
        for (int nt = 0; nt < 4; nt++)
            #pragma unroll
            for (int q = 0; q < 4; q++) acc[mt][nt][q] = 0.0f;

    auto load_chunk = [&](int kc) {
        #pragma unroll
        for (int tile = 0; tile < 4; ++tile) {
            #pragma unroll
            for (int q = 0; q < 4; ++q) {
                int uu = q * 256 + tid;           // 0..1023
                int row = uu >> 3;
                int seg = uu & 7;
                const __half* src = srcs[tile] + (size_t)row * D_ + kc * 64 + seg * 8;
                uint32_t dst = sbase + tile * CHUNK_BYTES + SWZ(row * 128 + seg * 16);
                CP_ASYNC16(dst, src);
            }
        }
    };

    int lr = lane & 15;
    int lc = (lane >> 4) * 16;

    auto compute_chunk = [&]() {
        uint32_t aH = sbase;
        uint32_t aL = aH + CHUNK_BYTES;
        uint32_t bH = aH + 2 * CHUNK_BYTES;
        uint32_t bL = aH + 3 * CHUNK_BYTES;
        #pragma unroll
        for (int ks = 0; ks < 4; ++ks) {
            int kb = ks * 32;
            uint32_t bh[4][2], bl[4][2];
            #pragma unroll
            for (int h = 0; h < 2; ++h) {
                int row = wn * 32 + h * 16 + lr;
                uint32_t off = SWZ(row * 128 + kb + lc);
                uint32_t r0, r1, r2, r3;
                LDSM_X4(r0, r1, r2, r3, bH + off);
                bh[2 * h + 0][0] = r0; bh[2 * h + 0][1] = r2;
                bh[2 * h + 1][0] = r1; bh[2 * h + 1][1] = r3;
                LDSM_X4(r0, r1, r2, r3, bL + off);
                bl[2 * h + 0][0] = r0; bl[2 * h + 0][1] = r2;
                bl[2 * h + 1][0] = r1; bl[2 * h + 1][1] = r3;
            }
            #pragma unroll
            for (int mt = 0; mt < 4; ++mt) {
                int row = wm * 64 + mt * 16 + lr;
                uint32_t off = SWZ(row * 128 + kb + lc);
                uint32_t ah[4], al[4];
                LDSM_X4(ah[0], ah[1], ah[2], ah[3], aH + off);
                LDSM_X4(al[0], al[1], al[2], al[3], aL + off);
                #pragma unroll
                for (int nt = 0; nt < 4; ++nt) {
                    MMA16816F16(acc[mt][nt], ah, bh[nt]);   // hh
                    MMA16816F16(acc[mt][nt], ah, bl[nt]);   // hl
                    MMA16816F16(acc[mt][nt], al, bh[nt]);   // lh
                }
            }
        }
    };

    // ---- main loop: single buffer; cross-CTA overlap hides load latency ----
    const int NCHUNK = D_ / 64;
    for (int kc = 0; kc < NCHUNK; ++kc) {
        load_chunk(kc);
        CP_COMMIT();
        CP_WAIT(0);
        __syncthreads();
        compute_chunk();
        __syncthreads();                  // before next load overwrites buffer
    }

    // ---- fused epilogue: threshold candidate extraction from registers ----
    int gi0 = ti * 128 + wm * 64 + (lane >> 2);      // fragment row base (in-batch)
    int gj0 = tj * 128 + wn * 32 + (lane & 3) * 2;   // fragment col base (in-batch)
    int rowbase = b * N_;
    bool offdiag = (ti != tj);

    #pragma unroll
    for (int mt = 0; mt < 4; ++mt)
        #pragma unroll
        for (int nt = 0; nt < 4; ++nt)
            #pragma unroll
            for (int q = 0; q < 4; ++q) {
                float v = acc[mt][nt][q];
                if (v > THRESH) {
                    int gi = gi0 + mt * 16 + ((q >> 1) << 3);
                    int gj = gj0 + nt * 8 + (q & 1);
                    int r1 = rowbase + gi;
                    int pos = atomicAdd(&g_cnt[r1], 1);
                    if (pos < CAND_MAX) {
                        g_candV[(size_t)r1 * CAND_MAX + pos] = v;
                        g_candI[(size_t)r1 * CAND_MAX + pos] = gj;
                    }
                    if (offdiag) {
                        int r2 = rowbase + gj;
                        int pos2 = atomicAdd(&g_cnt[r2], 1);
                        if (pos2 < CAND_MAX) {
                            g_candV[(size_t)r2 * CAND_MAX + pos2] = v;
                            g_candI[(size_t)r2 * CAND_MAX + pos2] = gi;
                        }
                    }
                }
            }
}

// ---------------------------------------------------------------------------
// Kernel 3: per-row exact top-32 over the candidate list + symmetric scatter.
// Fallback (count<K or overflow): recompute the full sim row in fp32 from
// the reconstructed (h+l) vectors and run the exact full top-k.
// ---------------------------------------------------------------------------
__global__ void __launch_bounds__(256) topk_scatter_kernel(float* __restrict__ out) {
    int row = blockIdx.x;                 // global row id
    int b = row >> 12;
    int i = row & (N_ - 1);
    int t = threadIdx.x;
    int lane = t & 31, warp = t >> 5;

    const float NEG_INF = __int_as_float(0xff800000);

    __shared__ float sV[K_];
    __shared__ int   sI[K_];

    int cnt = g_cnt[row];

    if (cnt >= K_ && cnt <= CAND_MAX) {
        // ---- fast path: warp 0 does exact top-32 over <=256 candidates ----
        if (warp == 0) {
            const float* cVr = g_candV + (size_t)row * CAND_MAX;
            const int*   cIr = g_candI + (size_t)row * CAND_MAX;
            float cv[8]; int ci[8];
            #pragma unroll
            for (int j = 0; j < 8; j++) {
                int idx = j * 32 + lane;
                bool ok = idx < cnt;
                cv[j] = ok ? cVr[idx] : NEG_INF;
                ci[j] = ok ? cIr[idx] : 0x7fffffff;
            }
            for (int r = 0; r < K_; r++) {
                float bv = cv[0]; int bi = ci[0];
                #pragma unroll
                for (int j = 1; j < 8; j++)
                    if (cv[j] > bv || (cv[j] == bv && ci[j] < bi)) { bv = cv[j]; bi = ci[j]; }
                #pragma unroll
                for (int o = 16; o; o >>= 1) {
                    float ov = __shfl_xor_sync(0xffffffffu, bv, o);
                    int   oi = __shfl_xor_sync(0xffffffffu, bi, o);
                    if (ov > bv || (ov == bv && oi < bi)) { bv = ov; bi = oi; }
                }
                if (lane == 0) { sV[r] = bv; sI[r] = bi; }
                #pragma unroll
                for (int j = 0; j < 8; j++)
                    if (ci[j] == bi) cv[j] = NEG_INF;
            }
        }
    } else {
        // ---- fallback: recompute full row, exact top-32 (rare/never) ----
        __shared__ float xb[D_];
        __shared__ float simbuf[N_];
        __shared__ float wV[8];
        __shared__ int   wI[8];

        const __half* hr = g_h + (size_t)row * D_;
        const __half* lr2 = g_l + (size_t)row * D_;
        for (int d = t; d < D_; d += 256)
            xb[d] = __half2float(hr[d]) + __half2float(lr2[d]);
        __syncthreads();

        for (int j = t; j < N_; j += 256) {
            const __half* hj = g_h + ((size_t)b * N_ + j) * D_;
            const __half* lj = g_l + ((size_t)b * N_ + j) * D_;
            float s = 0.0f;
            for (int d = 0; d < D_; d++)
                s = fmaf(xb[d], __half2float(hj[d]) + __half2float(lj[d]), s);
            simbuf[j] = s;
        }
        __syncthreads();

        float v[16];
        #pragma unroll
        for (int q = 0; q < 16; q++) v[q] = simbuf[warp * 512 + q * 32 + lane];

        for (int r = 0; r < K_; r++) {
            float bv = v[0]; int bq = 0;
            #pragma unroll
            for (int q = 1; q < 16; q++)
                if (v[q] > bv) { bv = v[q]; bq = q; }
            int bix = warp * 512 + bq * 32 + lane;

            #pragma unroll
            for (int o = 16; o; o >>= 1) {
                float ov = __shfl_xor_sync(0xffffffffu, bv, o);
                int   oi = __shfl_xor_sync(0xffffffffu, bix, o);
                if (ov > bv || (ov == bv && oi < bix)) { bv = ov; bix = oi; }
            }
            if (lane == 0) { wV[warp] = bv; wI[warp] = bix; }
            __syncthreads();
            if (t == 0) {
                float fv = wV[0]; int fi = wI[0];
                #pragma unroll
                for (int w = 1; w < 8; w++)
                    if (wV[w] > fv || (wV[w] == fv && wI[w] < fi)) { fv = wV[w]; fi = wI[w]; }
                sV[r] = fv; sI[r] = fi;
            }
            __syncthreads();
            int wi2 = sI[r];
            if ((wi2 & 511) == (warp * 32 + lane) % 512 && (wi2 >> 9) == warp)
                v[(wi2 >> 5) & 15] = NEG_INF;
            __syncthreads();
        }
    }
    __syncthreads();

    if (t < K_) {
        float val = 0.5f * sV[t];
        int j = sI[t];
        float* ob = out + (size_t)b * N_ * N_;
        atomicAdd(ob + (size_t)i * N_ + j, val);
        atomicAdd(ob + (size_t)j * N_ + i, val);
    }
}

// ---------------------------------------------------------------------------
extern "C" void kernel_launch(void* const* d_in, const int* in_sizes, int n_in,
                              void* d_out, int out_size) {
    const float* x = (const float*)d_in[0];
    float* out = (float*)d_out;

    cudaFuncSetAttribute(gemm_hmma_kernel,
                         cudaFuncAttributeMaxDynamicSharedMemorySize, SMEM_TOTAL);

    void* cnt_ptr = nullptr;
    cudaGetSymbolAddress(&cnt_ptr, g_cnt);

    cudaMemsetAsync(out, 0, (size_t)out_size * sizeof(float));
    cudaMemsetAsync(cnt_ptr, 0, NROWS * sizeof(int));
    normalize_kernel<<<B_ * N_, 128>>>(x);
    gemm_hmma_kernel<<<B_ * PAIRS, 256, SMEM_TOTAL>>>();
    topk_scatter_kernel<<<B_ * N_, 256>>>(out);
}

// round 12
// speedup vs baseline: 1.2439x; 1.2439x over previous
#include <cuda_runtime.h>
#include <cuda_fp16.h>
#include <cstdint>

// Problem constants
#define B_ 4
#define N_ 4096
#define D_ 512
#define K_ 32
#define TILES 32            // N_/128
#define PAIRS 528           // TILES*(TILES+1)/2

// Scratch (device globals — no runtime allocation allowed)
__device__ __align__(128) __half g_h[(size_t)B_ * N_ * D_];           // 16 MB
__device__ __align__(128) __half g_l[(size_t)B_ * N_ * D_];           // 16 MB
__device__ __align__(128) float g_sim[(size_t)B_ * N_ * N_];          // 268 MB

// ---------------------------------------------------------------------------
// Portable PTX helpers (compute_103-safe)
// ---------------------------------------------------------------------------
__device__ __forceinline__ uint32_t smem_u32(const void* p) {
    uint32_t a;
    asm("{ .reg .u64 t; cvta.to.shared.u64 t, %1; cvt.u32.u64 %0, t; }"
        : "=r"(a) : "l"(p));
    return a;
}

#define SWZ(off) ((off) ^ (((off) >> 3) & 0x70))

#define CP_ASYNC16(dst_u32, src_ptr) \
    asm volatile("cp.async.cg.shared.global [%0], [%1], 16;" \
                 :: "r"(dst_u32), "l"(src_ptr) : "memory")
#define CP_COMMIT() asm volatile("cp.async.commit_group;" ::: "memory")
#define CP_WAIT(n)  asm volatile("cp.async.wait_group %0;" :: "n"(n) : "memory")

#define LDSM_X4(r0, r1, r2, r3, addr) \
    asm volatile("ldmatrix.sync.aligned.m8n8.x4.shared.b16 {%0,%1,%2,%3}, [%4];" \
                 : "=r"(r0), "=r"(r1), "=r"(r2), "=r"(r3) : "r"(addr))

#define MMA16816F16(c, a, b) \
    asm volatile("mma.sync.aligned.m16n8k16.row.col.f32.f16.f16.f32 " \
                 "{%0,%1,%2,%3}, {%4,%5,%6,%7}, {%8,%9}, {%0,%1,%2,%3};" \
                 : "+f"((c)[0]), "+f"((c)[1]), "+f"((c)[2]), "+f"((c)[3]) \
                 : "r"((a)[0]), "r"((a)[1]), "r"((a)[2]), "r"((a)[3]), \
                   "r"((b)[0]), "r"((b)[1]))

// ---------------------------------------------------------------------------
// Kernel 1: row L2-normalization + fp16 2-limb split (unchanged).
// ---------------------------------------------------------------------------
__global__ void __launch_bounds__(128) normalize_kernel(const float* __restrict__ x) {
    int row = blockIdx.x;
    const float* xr = x + (size_t)row * D_;
    int t = threadIdx.x;

    float4 v = ((const float4*)xr)[t];
    float ss = v.x * v.x + v.y * v.y + v.z * v.z + v.w * v.w;
    #pragma unroll
    for (int o = 16; o; o >>= 1) ss += __shfl_xor_sync(0xffffffffu, ss, o);

    __shared__ float wsum[4];
    if ((t & 31) == 0) wsum[t >> 5] = ss;
    __syncthreads();
    float total = wsum[0] + wsum[1] + wsum[2] + wsum[3];
    float scale = 1.0f / fmaxf(sqrtf(total), 1e-12f);

    float xn[4] = {v.x * scale, v.y * scale, v.z * scale, v.w * scale};
    unsigned short hs[4], ls[4];
    #pragma unroll
    for (int q = 0; q < 4; q++) {
        __half h = __float2half_rn(xn[q]);
        float r1 = xn[q] - __half2float(h);
        __half l = __float2half_rn(r1);
        hs[q] = __half_as_ushort(h);
        ls[q] = __half_as_ushort(l);
    }
    uint2 hp, lp;
    hp.x = (uint32_t)hs[0] | ((uint32_t)hs[1] << 16);
    hp.y = (uint32_t)hs[2] | ((uint32_t)hs[3] << 16);
    lp.x = (uint32_t)ls[0] | ((uint32_t)ls[1] << 16);
    lp.y = (uint32_t)ls[2] | ((uint32_t)ls[3] << 16);
    ((uint2*)(g_h + (size_t)row * D_))[t] = hp;
    ((uint2*)(g_l + (size_t)row * D_))[t] = lp;
}

// ---------------------------------------------------------------------------
// Kernel 2: symmetric batched GEMM, fp16 2-limb 3-pass HMMA.
// 64x128 CTA tile (half-tile), 8 warps (2x4), warp tile 32x32,
// DOUBLE-buffered 48KB chunks AND 2 CTAs/SM (96KB smem/CTA).
// Per-element accumulation order (k16 ascending; hh,hl,lh) identical to
// R10 -> g_sim bitwise identical.
// ---------------------------------------------------------------------------
#define A_TILE 8192                       // 64 rows x 128B
#define B_TILE 16384                      // 128 rows x 128B
#define BUF_BYTES 49152                   // Ah+Al+Bh+Bl
#define SMEM_TOTAL (2 * BUF_BYTES)        // 98304; transpose (34816B) reuses it

__global__ void __launch_bounds__(256, 2) gemm_hmma_kernel() {
    extern __shared__ __align__(1024) char smem[];
    uint32_t sbase = smem_u32(smem);
    int tid = threadIdx.x;
    int wid = tid >> 5;
    int lane = tid & 31;

    int bidx = blockIdx.x;
    int half = bidx & 1;
    int pp = bidx >> 1;
    int b = pp / PAIRS;
    int u = pp % PAIRS;
    int ti = 0;
    while (u >= TILES - ti) { u -= TILES - ti; ti++; }
    int tj = ti + u;                      // tj >= ti

    size_t aoff = ((size_t)b * N_ + (size_t)ti * 128 + (size_t)half * 64) * D_;
    size_t boff = ((size_t)b * N_ + (size_t)tj * 128) * D_;
    const __half* Ah = g_h + aoff;
    const __half* Al = g_l + aoff;
    const __half* Bh = g_h + boff;
    const __half* Bl = g_l + boff;

    int wm = wid & 1;                     // 2 warps in M (32 rows each)
    int wn = wid >> 1;                    // 4 warps in N (32 cols each)

    float acc[2][4][4];
    #pragma unroll
    for (int mt = 0; mt < 2; mt++)
        #pragma unroll
        for (int nt = 0; nt < 4; nt++)
            #pragma unroll
            for (int q = 0; q < 4; q++) acc[mt][nt][q] = 0.0f;

    auto load_chunk = [&](int kc, int buf) {
        uint32_t base = sbase + buf * BUF_BYTES;
        // A limbs: 64 rows x 64 cols (8KB each)
        #pragma unroll
        for (int q = 0; q < 2; ++q) {
            int uu = q * 256 + tid;               // 0..511
            int row = uu >> 3;
            int seg = uu & 7;
            uint32_t sw = SWZ(row * 128 + seg * 16);
            CP_ASYNC16(base + sw, Ah + (size_t)row * D_ + kc * 64 + seg * 8);
            CP_ASYNC16(base + A_TILE + sw, Al + (size_t)row * D_ + kc * 64 + seg * 8);
        }
        // B limbs: 128 rows x 64 cols (16KB each)
        #pragma unroll
        for (int q = 0; q < 4; ++q) {
            int uu = q * 256 + tid;               // 0..1023
            int row = uu >> 3;
            int seg = uu & 7;
            uint32_t sw = SWZ(row * 128 + seg * 16);
            CP_ASYNC16(base + 2 * A_TILE + sw, Bh + (size_t)row * D_ + kc * 64 + seg * 8);
            CP_ASYNC16(base + 2 * A_TILE + B_TILE + sw, Bl + (size_t)row * D_ + kc * 64 + seg * 8);
        }
    };

    int lr = lane & 15;
    int lc = (lane >> 4) * 16;

    auto compute_chunk = [&](int buf) {
        uint32_t aHs = sbase + buf * BUF_BYTES;
        uint32_t aLs = aHs + A_TILE;
        uint32_t bHs = aHs + 2 * A_TILE;
        uint32_t bLs = bHs + B_TILE;
        #pragma unroll
        for (int ks = 0; ks < 4; ++ks) {
            int kb = ks * 32;
            uint32_t bh[4][2], bl[4][2];
            #pragma unroll
            for (int h = 0; h < 2; ++h) {
                int row = wn * 32 + h * 16 + lr;
                uint32_t off = SWZ(row * 128 + kb + lc);
                uint32_t r0, r1, r2, r3;
                LDSM_X4(r0, r1, r2, r3, bHs + off);
                bh[2 * h + 0][0] = r0; bh[2 * h + 0][1] = r2;
                bh[2 * h + 1][0] = r1; bh[2 * h + 1][1] = r3;
                LDSM_X4(r0, r1, r2, r3, bLs + off);
                bl[2 * h + 0][0] = r0; bl[2 * h + 0][1] = r2;
                bl[2 * h + 1][0] = r1; bl[2 * h + 1][1] = r3;
            }
            #pragma unroll
            for (int mt = 0; mt < 2; ++mt) {
                int row = wm * 32 + mt * 16 + lr;
                uint32_t off = SWZ(row * 128 + kb + lc);
                uint32_t ah[4], al[4];
                LDSM_X4(ah[0], ah[1], ah[2], ah[3], aHs + off);
                LDSM_X4(al[0], al[1], al[2], al[3], aLs + off);
                #pragma unroll
                for (int nt = 0; nt < 4; ++nt) {
                    MMA16816F16(acc[mt][nt], ah, bh[nt]);   // hh
                    MMA16816F16(acc[mt][nt], ah, bl[nt]);   // hl
                    MMA16816F16(acc[mt][nt], al, bh[nt]);   // lh
                }
            }
        }
    };

    // ---- pipelined main loop over 8 K-chunks (R6 double-buffer structure) ----
    const int NCHUNK = D_ / 64;
    load_chunk(0, 0); CP_COMMIT();
    for (int kc = 0; kc < NCHUNK; ++kc) {
        if (kc + 1 < NCHUNK) {
            load_chunk(kc + 1, (kc + 1) & 1); CP_COMMIT();
            CP_WAIT(1);
        } else {
            CP_WAIT(0);
        }
        __syncthreads();
        compute_chunk(kc & 1);
        __syncthreads();                  // before next load overwrites other buf
    }

    // ---- epilogue: direct tile (coalesced float2 per fragment row) ----
    float* C = g_sim + (size_t)b * N_ * N_;
    int r0 = ti * 128 + half * 64 + wm * 32 + (lane >> 2);
    int c0 = tj * 128 + wn * 32 + (lane & 3) * 2;
    #pragma unroll
    for (int mt = 0; mt < 2; ++mt)
        #pragma unroll
        for (int nt = 0; nt < 4; ++nt) {
            float2 v01 = make_float2(acc[mt][nt][0], acc[mt][nt][1]);
            float2 v23 = make_float2(acc[mt][nt][2], acc[mt][nt][3]);
            *(float2*)(C + (size_t)(r0 + mt * 16) * N_ + c0 + nt * 8)     = v01;
            *(float2*)(C + (size_t)(r0 + mt * 16 + 8) * N_ + c0 + nt * 8) = v23;
        }

    // ---- mirror (off-diag): smem transpose 128 cols x 64 rows, stride 68 ----
    if (ti != tj) {
        float* T = (float*)smem;          // [128][68] floats = 34816 B
        int rl = wm * 32 + (lane >> 2);   // 0..63 (row within half-tile)
        int cl = wn * 32 + (lane & 3) * 2;
        #pragma unroll
        for (int mt = 0; mt < 2; ++mt)
            #pragma unroll
            for (int nt = 0; nt < 4; ++nt) {
                int rr = rl + mt * 16;
                int cc = cl + nt * 8;
                T[(cc + 0) * 68 + rr]     = acc[mt][nt][0];
                T[(cc + 1) * 68 + rr]     = acc[mt][nt][1];
                T[(cc + 0) * 68 + rr + 8] = acc[mt][nt][2];
                T[(cc + 1) * 68 + rr + 8] = acc[mt][nt][3];
            }
        __syncthreads();
        int jb = tj * 128, ib = ti * 128 + half * 64;
        #pragma unroll
        for (int q = 0; q < 8; ++q) {
            int uu = q * 256 + tid;       // 0..2047
            int r = uu >> 4;              // 0..127 (mirror row = original col)
            int c4 = uu & 15;             // float4 index within 64-float row
            float4 v = *(float4*)&T[r * 68 + c4 * 4];
            *(float4*)(C + (size_t)(jb + r) * N_ + ib + c4 * 4) = v;
        }
    }
}

// ---------------------------------------------------------------------------
// Kernel 3: threshold-pruned top-32 + exact fallback (unchanged from R9/R10).
// ---------------------------------------------------------------------------
#define THRESH 0.09f
#define CAND_MAX 256

__global__ void __launch_bounds__(256) topk_scatter_kernel(float* __restrict__ out) {
    int row = blockIdx.x;
    int b = row >> 12;
    int i = row & (N_ - 1);
    const float* srow = g_sim + (size_t)b * N_ * N_ + (size_t)i * N_;
    int t = threadIdx.x;
    int lane = t & 31, warp = t >> 5;

    const float NEG_INF = __int_as_float(0xff800000);

    __shared__ float cV[CAND_MAX];
    __shared__ int   cI[CAND_MAX];
    __shared__ int   scnt;
    __shared__ float sV[K_];
    __shared__ int   sI[K_];
    if (t == 0) scnt = 0;
    __syncthreads();

    float v[16];
    #pragma unroll
    for (int q = 0; q < 16; q++) v[q] = srow[warp * 512 + q * 32 + lane];

    #pragma unroll
    for (int q = 0; q < 16; q++) {
        bool p = v[q] > THRESH;
        unsigned mask = __ballot_sync(0xffffffffu, p);
        if (mask) {
            int base = 0;
            if (lane == 0) base = atomicAdd(&scnt, __popc(mask));
            base = __shfl_sync(0xffffffffu, base, 0);
            if (p) {
                int pos = base + __popc(mask & ((1u << lane) - 1));
                if (pos < CAND_MAX) {
                    cV[pos] = v[q];
                    cI[pos] = warp * 512 + q * 32 + lane;
                }
            }
        }
    }
    __syncthreads();
    int cnt = scnt;

    if (cnt >= K_ && cnt <= CAND_MAX) {
        if (warp == 0) {
            float cv[8]; int ci[8];
            #pragma unroll
            for (int j = 0; j < 8; j++) {
                int idx = j * 32 + lane;
                bool ok = idx < cnt;
                cv[j] = ok ? cV[idx] : NEG_INF;
                ci[j] = ok ? cI[idx] : 0x7fffffff;
            }
            for (int r = 0; r < K_; r++) {
                float bv = cv[0]; int bi = ci[0];
                #pragma unroll
                for (int j = 1; j < 8; j++)
                    if (cv[j] > bv || (cv[j] == bv && ci[j] < bi)) { bv = cv[j]; bi = ci[j]; }
                #pragma unroll
                for (int o = 16; o; o >>= 1) {
                    float ov = __shfl_xor_sync(0xffffffffu, bv, o);
                    int   oi = __shfl_xor_sync(0xffffffffu, bi, o);
                    if (ov > bv || (ov == bv && oi < bi)) { bv = ov; bi = oi; }
                }
                if (lane == 0) { sV[r] = bv; sI[r] = bi; }
                #pragma unroll
                for (int j = 0; j < 8; j++)
                    if (ci[j] == bi) cv[j] = NEG_INF;
            }
        }
    } else {
        for (int r = 0; r < K_; r++) {
            float bv = v[0]; int bq = 0;
            #pragma unroll
            for (int q = 1; q < 16; q++)
                if (v[q] > bv) { bv = v[q]; bq = q; }
            int bix = warp * 512 + bq * 32 + lane;

            #pragma unroll
            for (int o = 16; o; o >>= 1) {
                float ov = __shfl_xor_sync(0xffffffffu, bv, o);
                int   oi = __shfl_xor_sync(0xffffffffu, bix, o);
                if (ov > bv || (ov == bv && oi < bix)) { bv = ov; bix = oi; }
            }
            if (lane == 0) { cV[warp * 32 + r] = bv; cI[warp * 32 + r] = bix; }
            if ((bix & 31) == lane) v[(bix >> 5) & 15] = NEG_INF;
            __syncwarp();
        }
        __syncthreads();
        if (warp == 0) {
            float cv[8]; int ci[8];
            #pragma unroll
            for (int j = 0; j < 8; j++) { cv[j] = cV[j * 32 + lane]; ci[j] = cI[j * 32 + lane]; }
            for (int r = 0; r < K_; r++) {
                float bv = cv[0]; int bi = ci[0];
                #pragma unroll
                for (int j = 1; j < 8; j++)
                    if (cv[j] > bv || (cv[j] == bv && ci[j] < bi)) { bv = cv[j]; bi = ci[j]; }
                #pragma unroll
                for (int o = 16; o; o >>= 1) {
                    float ov = __shfl_xor_sync(0xffffffffu, bv, o);
                    int   oi = __shfl_xor_sync(0xffffffffu, bi, o);
                    if (ov > bv || (ov == bv && oi < bi)) { bv = ov; bi = oi; }
                }
                if (lane == 0) { sV[r] = bv; sI[r] = bi; }
                #pragma unroll
                for (int j = 0; j < 8; j++)
                    if (ci[j] == bi) cv[j] = NEG_INF;
            }
        }
    }
    __syncthreads();

    if (t < K_) {
        float val = 0.5f * sV[t];
        int j = sI[t];
        float* ob = out + (size_t)b * N_ * N_;
        atomicAdd(ob + (size_t)i * N_ + j, val);
        atomicAdd(ob + (size_t)j * N_ + i, val);
    }
}

// ---------------------------------------------------------------------------
extern "C" void kernel_launch(void* const* d_in, const int* in_sizes, int n_in,
                              void* d_out, int out_size) {
    const float* x = (const float*)d_in[0];
    float* out = (float*)d_out;

    cudaFuncSetAttribute(gemm_hmma_kernel,
                         cudaFuncAttributeMaxDynamicSharedMemorySize, SMEM_TOTAL);

    cudaMemsetAsync(out, 0, (size_t)out_size * sizeof(float));
    normalize_kernel<<<B_ * N_, 128>>>(x);
    gemm_hmma_kernel<<<B_ * PAIRS * 2, 256, SMEM_TOTAL>>>();
    topk_scatter_kernel<<<B_ * N_, 256>>>(out);
}